// round 1
// baseline (speedup 1.0000x reference)
#include <cuda_runtime.h>
#include <cuda_bf16.h>

#define EPS_EYE 1e-07f
#define BLK 256

__global__ __launch_bounds__(BLK)
void cov3d_kernel(const float* __restrict__ scaling,
                  const float* __restrict__ rotation,
                  float* __restrict__ out,
                  int N)
{
    __shared__ float s_scl[BLK * 3];   // 3072 B
    __shared__ float s_out[BLK * 9];   // 9216 B

    const int tid  = threadIdx.x;
    const int base = blockIdx.x * BLK;
    const bool full = (base + BLK) <= N;

    float sx, sy, sz;
    float4 q;

    if (full) {
        // Stage scaling through smem with vectorized loads.
        // base*3 = 768*blockIdx -> float4-aligned offset.
        const float4* src = reinterpret_cast<const float4*>(scaling + (size_t)base * 3);
        if (tid < (BLK * 3) / 4) {
            reinterpret_cast<float4*>(s_scl)[tid] = src[tid];
        }
        q = reinterpret_cast<const float4*>(rotation)[base + tid];
        __syncthreads();
        sx = s_scl[tid * 3 + 0];
        sy = s_scl[tid * 3 + 1];
        sz = s_scl[tid * 3 + 2];
    } else {
        int n = base + tid;
        if (n < N) {
            sx = scaling[(size_t)n * 3 + 0];
            sy = scaling[(size_t)n * 3 + 1];
            sz = scaling[(size_t)n * 3 + 2];
            q  = reinterpret_cast<const float4*>(rotation)[n];
        } else {
            sx = sy = sz = 0.f;
            q = make_float4(1.f, 0.f, 0.f, 0.f);
        }
    }

    // s = exp(scaling); we need s^2 in the covariance.
    float ex = __expf(sx), ey = __expf(sy), ez = __expf(sz);
    float a = ex * ex, b = ey * ey, c = ez * ez;

    // Normalize quaternion (x,y,z,w) = (q.x,q.y,q.z,q.w) per reference order.
    float x = q.x, y = q.y, z = q.z, w = q.w;
    float inv = rsqrtf(x * x + y * y + z * z + w * w);
    x *= inv; y *= inv; z *= inv; w *= inv;

    float xx = x * x, yy = y * y, zz = z * z;
    float xy = x * y, xz = x * z, yz = y * z;
    float wx = w * x, wy = w * y, wz = w * z;

    float r00 = 1.f - 2.f * (yy + zz);
    float r01 = 2.f * (xy - wz);
    float r02 = 2.f * (xz + wy);
    float r10 = 2.f * (xy + wz);
    float r11 = 1.f - 2.f * (xx + zz);
    float r12 = 2.f * (yz - wx);
    float r20 = 2.f * (xz - wy);
    float r21 = 2.f * (yz + wx);
    float r22 = 1.f - 2.f * (xx + yy);

    // cov[i][j] = sum_k R[i][k]*R[j][k]*s_k^2  (exactly symmetric in fp)
    float c00 = r00 * r00 * a + r01 * r01 * b + r02 * r02 * c + EPS_EYE;
    float c01 = r00 * r10 * a + r01 * r11 * b + r02 * r12 * c;
    float c02 = r00 * r20 * a + r01 * r21 * b + r02 * r22 * c;
    float c11 = r10 * r10 * a + r11 * r11 * b + r12 * r12 * c + EPS_EYE;
    float c12 = r10 * r20 * a + r11 * r21 * b + r12 * r22 * c;
    float c22 = r20 * r20 * a + r21 * r21 * b + r22 * r22 * c + EPS_EYE;

    if (full) {
        // Stride-9 smem writes: gcd(9,32)=1 -> conflict-free.
        float* o = s_out + tid * 9;
        o[0] = c00; o[1] = c01; o[2] = c02;
        o[3] = c01; o[4] = c11; o[5] = c12;
        o[6] = c02; o[7] = c12; o[8] = c22;
        __syncthreads();
        // Coalesced vectorized flush: 2304 floats = 576 float4.
        float4* dst = reinterpret_cast<float4*>(out + (size_t)base * 9);
        const float4* s4 = reinterpret_cast<const float4*>(s_out);
        #pragma unroll
        for (int i = tid; i < (BLK * 9) / 4; i += BLK) {
            dst[i] = s4[i];
        }
    } else {
        int n = base + tid;
        if (n < N) {
            float* o = out + (size_t)n * 9;
            o[0] = c00; o[1] = c01; o[2] = c02;
            o[3] = c01; o[4] = c11; o[5] = c12;
            o[6] = c02; o[7] = c12; o[8] = c22;
        }
    }
}

extern "C" void kernel_launch(void* const* d_in, const int* in_sizes, int n_in,
                              void* d_out, int out_size)
{
    const float* scaling  = (const float*)d_in[0];   // (N,3)
    const float* rotation = (const float*)d_in[1];   // (N,4)
    float* out = (float*)d_out;                      // (N,3,3)
    int N = in_sizes[0] / 3;
    int grid = (N + BLK - 1) / BLK;
    cov3d_kernel<<<grid, BLK>>>(scaling, rotation, out, N);
}

// round 2
// speedup vs baseline: 1.0136x; 1.0136x over previous
#include <cuda_runtime.h>
#include <cuda_bf16.h>

#define EPS_EYE 1e-07f
#define BLK 256
#define PTS_PER_BLK (BLK * 2)

__device__ __forceinline__ void compute_cov(float sx, float sy, float sz,
                                            float4 q, float* __restrict__ o)
{
    float ex = __expf(sx), ey = __expf(sy), ez = __expf(sz);
    float a = ex * ex, b = ey * ey, c = ez * ez;

    float x = q.x, y = q.y, z = q.z, w = q.w;
    float inv = rsqrtf(x * x + y * y + z * z + w * w);
    x *= inv; y *= inv; z *= inv; w *= inv;

    float xx = x * x, yy = y * y, zz = z * z;
    float xy = x * y, xz = x * z, yz = y * z;
    float wx = w * x, wy = w * y, wz = w * z;

    float r00 = 1.f - 2.f * (yy + zz);
    float r01 = 2.f * (xy - wz);
    float r02 = 2.f * (xz + wy);
    float r10 = 2.f * (xy + wz);
    float r11 = 1.f - 2.f * (xx + zz);
    float r12 = 2.f * (yz - wx);
    float r20 = 2.f * (xz - wy);
    float r21 = 2.f * (yz + wx);
    float r22 = 1.f - 2.f * (xx + yy);

    float c00 = r00 * r00 * a + r01 * r01 * b + r02 * r02 * c + EPS_EYE;
    float c01 = r00 * r10 * a + r01 * r11 * b + r02 * r12 * c;
    float c02 = r00 * r20 * a + r01 * r21 * b + r02 * r22 * c;
    float c11 = r10 * r10 * a + r11 * r11 * b + r12 * r12 * c + EPS_EYE;
    float c12 = r10 * r20 * a + r11 * r21 * b + r12 * r22 * c;
    float c22 = r20 * r20 * a + r21 * r21 * b + r22 * r22 * c + EPS_EYE;

    o[0] = c00; o[1] = c01; o[2] = c02;
    o[3] = c01; o[4] = c11; o[5] = c12;
    o[6] = c02; o[7] = c12; o[8] = c22;
}

__global__ __launch_bounds__(BLK)
void cov3d_kernel(const float* __restrict__ scaling,
                  const float* __restrict__ rotation,
                  float* __restrict__ out,
                  int N)
{
    __shared__ float s_out[PTS_PER_BLK * 9];   // 18432 B

    const int tid  = threadIdx.x;
    const int base = blockIdx.x * PTS_PER_BLK;
    const bool full = (base + PTS_PER_BLK) <= N;

    if (full) {
        const int n0 = base + tid;
        const int n1 = n0 + BLK;

        // Front-batched loads: MLP = 8 per thread.
        float4 q0 = __ldcs(reinterpret_cast<const float4*>(rotation) + n0);
        float4 q1 = __ldcs(reinterpret_cast<const float4*>(rotation) + n1);
        float s0x = __ldcs(scaling + (size_t)n0 * 3 + 0);
        float s0y = __ldcs(scaling + (size_t)n0 * 3 + 1);
        float s0z = __ldcs(scaling + (size_t)n0 * 3 + 2);
        float s1x = __ldcs(scaling + (size_t)n1 * 3 + 0);
        float s1y = __ldcs(scaling + (size_t)n1 * 3 + 1);
        float s1z = __ldcs(scaling + (size_t)n1 * 3 + 2);

        // Stride-9 smem writes: gcd(9,32)=1 -> conflict-free.
        compute_cov(s0x, s0y, s0z, q0, s_out + tid * 9);
        compute_cov(s1x, s1y, s1z, q1, s_out + (tid + BLK) * 9);

        __syncthreads();

        // Coalesced streaming flush: 4608 floats = 1152 float4.
        float4* dst = reinterpret_cast<float4*>(out + (size_t)base * 9);
        const float4* s4 = reinterpret_cast<const float4*>(s_out);
        #pragma unroll
        for (int i = tid; i < (PTS_PER_BLK * 9) / 4; i += BLK) {
            __stcs(dst + i, s4[i]);
        }
    } else {
        #pragma unroll
        for (int k = 0; k < 2; k++) {
            int n = base + tid + k * BLK;
            if (n < N) {
                float4 q = reinterpret_cast<const float4*>(rotation)[n];
                float sx = scaling[(size_t)n * 3 + 0];
                float sy = scaling[(size_t)n * 3 + 1];
                float sz = scaling[(size_t)n * 3 + 2];
                float o[9];
                compute_cov(sx, sy, sz, q, o);
                float* dst = out + (size_t)n * 9;
                #pragma unroll
                for (int i = 0; i < 9; i++) dst[i] = o[i];
            }
        }
    }
}

extern "C" void kernel_launch(void* const* d_in, const int* in_sizes, int n_in,
                              void* d_out, int out_size)
{
    const float* scaling  = (const float*)d_in[0];   // (N,3)
    const float* rotation = (const float*)d_in[1];   // (N,4)
    float* out = (float*)d_out;                      // (N,3,3)
    int N = in_sizes[0] / 3;
    int grid = (N + PTS_PER_BLK - 1) / PTS_PER_BLK;
    cov3d_kernel<<<grid, BLK>>>(scaling, rotation, out, N);
}

// round 3
// speedup vs baseline: 1.0262x; 1.0125x over previous
#include <cuda_runtime.h>
#include <cuda_bf16.h>
#include <cstdint>

#define EPS_EYE 1e-07f
#define BLK 256
#define PTS_PER_BLK (BLK * 2)
#define TILE_BYTES (PTS_PER_BLK * 9 * 4)   // 18432

__device__ __forceinline__ uint32_t smem_u32(const void* p) {
    uint32_t a;
    asm("{ .reg .u64 t; cvta.to.shared.u64 t, %1; cvt.u32.u64 %0, t; }"
        : "=r"(a) : "l"(p));
    return a;
}

__device__ __forceinline__ void compute_cov(float sx, float sy, float sz,
                                            float4 q, float* __restrict__ o)
{
    float ex = __expf(sx), ey = __expf(sy), ez = __expf(sz);
    float a = ex * ex, b = ey * ey, c = ez * ez;

    float x = q.x, y = q.y, z = q.z, w = q.w;
    float inv = rsqrtf(x * x + y * y + z * z + w * w);
    x *= inv; y *= inv; z *= inv; w *= inv;

    float xx = x * x, yy = y * y, zz = z * z;
    float xy = x * y, xz = x * z, yz = y * z;
    float wx = w * x, wy = w * y, wz = w * z;

    float r00 = 1.f - 2.f * (yy + zz);
    float r01 = 2.f * (xy - wz);
    float r02 = 2.f * (xz + wy);
    float r10 = 2.f * (xy + wz);
    float r11 = 1.f - 2.f * (xx + zz);
    float r12 = 2.f * (yz - wx);
    float r20 = 2.f * (xz - wy);
    float r21 = 2.f * (yz + wx);
    float r22 = 1.f - 2.f * (xx + yy);

    float c00 = r00 * r00 * a + r01 * r01 * b + r02 * r02 * c + EPS_EYE;
    float c01 = r00 * r10 * a + r01 * r11 * b + r02 * r12 * c;
    float c02 = r00 * r20 * a + r01 * r21 * b + r02 * r22 * c;
    float c11 = r10 * r10 * a + r11 * r11 * b + r12 * r12 * c + EPS_EYE;
    float c12 = r10 * r20 * a + r11 * r21 * b + r12 * r22 * c;
    float c22 = r20 * r20 * a + r21 * r21 * b + r22 * r22 * c + EPS_EYE;

    o[0] = c00; o[1] = c01; o[2] = c02;
    o[3] = c01; o[4] = c11; o[5] = c12;
    o[6] = c02; o[7] = c12; o[8] = c22;
}

__global__ __launch_bounds__(BLK)
void cov3d_kernel(const float* __restrict__ scaling,
                  const float* __restrict__ rotation,
                  float* __restrict__ out,
                  int N)
{
    __shared__ __align__(16) float s_out[PTS_PER_BLK * 9];   // 18432 B

    const int tid  = threadIdx.x;
    const int base = blockIdx.x * PTS_PER_BLK;
    const bool full = (base + PTS_PER_BLK) <= N;

    if (full) {
        const int n0 = base + tid;
        const int n1 = n0 + BLK;

        // Front-batched loads: MLP = 8 per thread.
        float4 q0 = __ldcs(reinterpret_cast<const float4*>(rotation) + n0);
        float4 q1 = __ldcs(reinterpret_cast<const float4*>(rotation) + n1);
        float s0x = __ldcs(scaling + (size_t)n0 * 3 + 0);
        float s0y = __ldcs(scaling + (size_t)n0 * 3 + 1);
        float s0z = __ldcs(scaling + (size_t)n0 * 3 + 2);
        float s1x = __ldcs(scaling + (size_t)n1 * 3 + 0);
        float s1y = __ldcs(scaling + (size_t)n1 * 3 + 1);
        float s1z = __ldcs(scaling + (size_t)n1 * 3 + 2);

        // Stride-9 smem writes: gcd(9,32)=1 -> conflict-free.
        compute_cov(s0x, s0y, s0z, q0, s_out + tid * 9);
        compute_cov(s1x, s1y, s1z, q1, s_out + (tid + BLK) * 9);

        __syncthreads();

        // Single TMA bulk store: smem tile -> gmem, perfect 128B write bursts.
        if (tid == 0) {
            // Order generic-proxy smem writes before async-proxy read.
            asm volatile("fence.proxy.async.shared::cta;" ::: "memory");
            uint32_t saddr = smem_u32(s_out);
            const float* gdst = out + (size_t)base * 9;
            asm volatile(
                "cp.async.bulk.global.shared::cta.bulk_group [%0], [%1], %2;"
                :: "l"(gdst), "r"(saddr), "n"(TILE_BYTES)
                : "memory");
            asm volatile("cp.async.bulk.commit_group;" ::: "memory");
            // Must complete before CTA exit (smem lifetime).
            asm volatile("cp.async.bulk.wait_group.read 0;" ::: "memory");
        }
    } else {
        #pragma unroll
        for (int k = 0; k < 2; k++) {
            int n = base + tid + k * BLK;
            if (n < N) {
                float4 q = reinterpret_cast<const float4*>(rotation)[n];
                float sx = scaling[(size_t)n * 3 + 0];
                float sy = scaling[(size_t)n * 3 + 1];
                float sz = scaling[(size_t)n * 3 + 2];
                float o[9];
                compute_cov(sx, sy, sz, q, o);
                float* dst = out + (size_t)n * 9;
                #pragma unroll
                for (int i = 0; i < 9; i++) dst[i] = o[i];
            }
        }
    }
}

extern "C" void kernel_launch(void* const* d_in, const int* in_sizes, int n_in,
                              void* d_out, int out_size)
{
    const float* scaling  = (const float*)d_in[0];   // (N,3)
    const float* rotation = (const float*)d_in[1];   // (N,4)
    float* out = (float*)d_out;                      // (N,3,3)
    int N = in_sizes[0] / 3;
    int grid = (N + PTS_PER_BLK - 1) / PTS_PER_BLK;
    cov3d_kernel<<<grid, BLK>>>(scaling, rotation, out, N);
}